// round 8
// baseline (speedup 1.0000x reference)
#include <cuda_runtime.h>

#define UNITS 128
#define WIN   1024
#define JT    8              // j-rows per block
#define NBLK  (WIN / JT)     // 128 blocks (best measured topology)
#define KS    16             // k-slice per warp (8 warps * 16 = 128)

// Interleaved accumulators: g_acc[2u] = sum e, g_acc[2u+1] = sum e*fs.
// Zero at load; last block resets them so graph replays stay correct.
__device__ float        g_acc[2 * UNITS];
__device__ unsigned int g_count;

// Ticket with acq_rel semantics: release publishes this block's REDGs
// (ordered by the preceding bar.sync, cumulative), acquire pulls in all
// other blocks' REDGs for the epilogue.
__device__ __forceinline__ unsigned int ticket_acq_rel(unsigned int* p) {
    unsigned int old;
    asm volatile("atom.acq_rel.gpu.add.u32 %0, [%1], 1;"
                 : "=r"(old) : "l"(p) : "memory");
    return old;
}

// ---------------------------------------------------------------------------
// Fused split-K kernel, tail-pruned.
// Identity: logit[j,u] = sum_k fs[j,k] * (w_hi[k,u] + input[k]*w_dot[u])
// (dot-product term folded into the weights). Softmax shift-invariant and
// |logit| small -> no max subtraction (fp32-safe).
//
// 128 blocks x 256 threads. fs-gather LDGs issue FIRST (L1tex FIFO: they gate
// the first barrier; the w regs aren't needed until after it). Warp w owns
// k in [16w,16w+16): 16 independent LDG.128 into registers, folded with
// direct input[] reads. GEMM over smem fs tile, one-stage cross-warp reduce,
// exp, per-u block reduce, REDG pair, release-ticket + bar.red.or epilogue.
// ---------------------------------------------------------------------------
__global__ __launch_bounds__(256, 1) void rsa_fused6_kernel(
    const float* __restrict__ input,   // [128]
    const float* __restrict__ state,   // [128][1024]
    const float* __restrict__ w,       // [257][128]
    float* __restrict__ out)           // [128]
{
    __shared__ float fs_s[JT][UNITS];        // fs tile [jj][k]      (4 KB)
    __shared__ float part[8][JT][UNITS];     // split-K partials     (32 KB)

    const int tid  = threadIdx.x;
    const int wid  = tid >> 5;
    const int lane = tid & 31;
    const int u0   = lane * 4;
    const int j0   = blockIdx.x * JT;
    const int k0   = wid * KS;

    // 1) fs gather FIRST: fs[j,k] = state[k, j+1] (j < 1023) else input[k].
    //    These loads gate the first barrier -> lowest L1tex queue positions.
    #pragma unroll
    for (int idx = tid; idx < JT * UNITS; idx += 256) {
        int k  = idx >> 3;
        int jj = idx & (JT - 1);
        int j  = j0 + jj;
        fs_s[jj][k] = (j < WIN - 1) ? state[k * WIN + j + 1] : input[k];
    }

    // 2) w front-load: w_dot row, 16 independent LDG.128, input slice.
    const float4 wd = *reinterpret_cast<const float4*>(&w[2 * UNITS * UNITS + u0]);
    float4 wreg[KS];
    #pragma unroll
    for (int k = 0; k < KS; ++k)
        wreg[k] = *reinterpret_cast<const float4*>(&w[(k0 + k) * UNITS + u0]);

    float ivf[KS];
    #pragma unroll
    for (int i = 0; i < KS / 4; ++i) {
        float4 iv = *reinterpret_cast<const float4*>(&input[k0 + 4 * i]);
        ivf[4 * i + 0] = iv.x;
        ivf[4 * i + 1] = iv.y;
        ivf[4 * i + 2] = iv.z;
        ivf[4 * i + 3] = iv.w;
    }

    // 3) Fold: w_eff[k,u] = w_hi[k,u] + input[k]*w_dot[u]  (registers only)
    #pragma unroll
    for (int k = 0; k < KS; ++k) {
        wreg[k].x += ivf[k] * wd.x;
        wreg[k].y += ivf[k] * wd.y;
        wreg[k].z += ivf[k] * wd.z;
        wreg[k].w += ivf[k] * wd.w;
    }
    __syncthreads();

    // 4) Split-K partial GEMM: acc[j][u0..3] over this warp's 16 k's.
    float4 acc[JT];
    #pragma unroll
    for (int j = 0; j < JT; ++j) acc[j] = make_float4(0.f, 0.f, 0.f, 0.f);

    #pragma unroll
    for (int k = 0; k < KS; ++k) {
        const float4 wv = wreg[k];
        #pragma unroll
        for (int j = 0; j < JT; ++j) {
            float f = fs_s[j][k0 + k];          // smem broadcast, conflict-free
            acc[j].x += f * wv.x;
            acc[j].y += f * wv.y;
            acc[j].z += f * wv.z;
            acc[j].w += f * wv.w;
        }
    }
    #pragma unroll
    for (int j = 0; j < JT; ++j)
        *reinterpret_cast<float4*>(&part[wid][j][u0]) = acc[j];
    __syncthreads();

    // 5) Cross-warp reduce -> logit -> e. Thread owns (j=wid, u0).
    //    e overlays part[0] (owner-exclusive read-then-write, safe).
    {
        const int j = wid;
        float4 sum = make_float4(0.f, 0.f, 0.f, 0.f);
        #pragma unroll
        for (int r = 0; r < 8; ++r) {
            float4 p = *reinterpret_cast<const float4*>(&part[r][j][u0]);
            sum.x += p.x; sum.y += p.y; sum.z += p.z; sum.w += p.w;
        }
        float4 e;
        e.x = __expf(sum.x);
        e.y = __expf(sum.y);
        e.z = __expf(sum.z);
        e.w = __expf(sum.w);
        *reinterpret_cast<float4*>(&part[0][j][u0]) = e;
    }
    __syncthreads();

    // 6) Per-u reduce over this block's 8 j rows, one adjacent REDG pair.
    if (tid < UNITS) {
        float s = 0.f, ws = 0.f;
        #pragma unroll
        for (int r = 0; r < JT; ++r) {
            float e = part[0][r][tid];
            s  += e;
            ws += e * fs_s[r][tid];
        }
        atomicAdd(&g_acc[2 * tid + 0], s);
        atomicAdd(&g_acc[2 * tid + 1], ws);
    }
    __syncthreads();   // all REDGs issued & program-ordered before the ticket

    // 7) Release-ticket + single bar.red.or broadcast (no threadfence,
    //    no smem flag, one barrier instead of two).
    int pred = 0;
    if (tid == 0)
        pred = (ticket_acq_rel(&g_count) == (unsigned)(NBLK - 1));
    const int last = __syncthreads_or(pred);

    if (last) {
        if (tid < UNITS) {
            // ticket acquire happened-before this (via the bar) => all blocks'
            // REDGs visible; .cg bypasses (launch-stale) L1, reads L2.
            float S  = __ldcg(&g_acc[2 * tid + 0]);
            float WS = __ldcg(&g_acc[2 * tid + 1]);
            out[tid] = WS / S;
            g_acc[2 * tid + 0] = 0.f;         // reset for next graph replay
            g_acc[2 * tid + 1] = 0.f;
        }
        __syncthreads();
        if (tid == 0) g_count = 0u;
    }
}

// ---------------------------------------------------------------------------
extern "C" void kernel_launch(void* const* d_in, const int* in_sizes, int n_in,
                              void* d_out, int out_size) {
    const float* input = (const float*)d_in[0];   // (1, 128)
    const float* state = (const float*)d_in[1];   // (128, 1024)
    const float* w     = (const float*)d_in[2];   // (257, 128)
    // d_in[3] = b cancels in the softmax -> unused
    float* out = (float*)d_out;                   // (1, 128)

    rsa_fused6_kernel<<<NBLK, 256>>>(input, state, w, out);
}